// round 9
// baseline (speedup 1.0000x reference)
#include <cuda_runtime.h>
#include <cuda_bf16.h>
#include <math.h>
#include <cstdint>

#define Bsz   64
#define Lseq  512
#define Edim  512
#define Hdim  1024
#define H2    2048

// ---------------------------------------------------------------------------
// Scratch (device globals; no runtime allocation allowed)
// ---------------------------------------------------------------------------
__device__ float g_PRE[4u * 2048u * 2048u]; // split-K partial slabs (small levels only)
__device__ float g_Zb [16384u * 1024u];     // z gate per pair
__device__ float g_H0 [32768u * 1024u];     // state ping (fp32)
__device__ float g_H1 [16384u * 1024u];     // state pong (fp32)
// bf16 hi/lo split activations
__device__ __nv_bfloat16 g_Wh [32768u * 512u];
__device__ __nv_bfloat16 g_Wl [32768u * 512u];
__device__ __nv_bfloat16 g_H0h[32768u * 1024u];
__device__ __nv_bfloat16 g_H0l[32768u * 1024u];
__device__ __nv_bfloat16 g_H1h[16384u * 1024u];
__device__ __nv_bfloat16 g_H1l[16384u * 1024u];
__device__ __nv_bfloat16 g_Qh [16384u * 2048u];
__device__ __nv_bfloat16 g_Ql [16384u * 2048u];
// Transposed [N,K] weights split to bf16 hi/lo.
// WzhT: N interleaved as (z_j, h_j) pairs. UzrT: N interleaved as (z_j, r_j).
__device__ __nv_bfloat16 g_WzhT_h[(size_t)H2 * Edim];
__device__ __nv_bfloat16 g_WzhT_l[(size_t)H2 * Edim];
__device__ __nv_bfloat16 g_UzrT_h[(size_t)H2 * H2];
__device__ __nv_bfloat16 g_UzrT_l[(size_t)H2 * H2];
__device__ __nv_bfloat16 g_UhT_h [(size_t)Hdim * H2];
__device__ __nv_bfloat16 g_UhT_l [(size_t)Hdim * H2];
__device__ float g_bz[Hdim], g_br[Hdim], g_bh[Hdim];

// ---------------------------------------------------------------------------
// Helpers
// ---------------------------------------------------------------------------
__device__ __forceinline__ uint32_t smem_u32(const void* p) {
    uint32_t a;
    asm("{ .reg .u64 t; cvta.to.shared.u64 t, %1; cvt.u32.u64 %0, t; }" : "=r"(a) : "l"(p));
    return a;
}
__device__ __forceinline__ uint32_t swz64(uint32_t row, uint32_t byte) {
    return row * 64u + (byte ^ (((row >> 1) & 3u) << 4));
}
__device__ __forceinline__ void cp16(uint32_t dst, const void* src, uint32_t srcsize) {
    asm volatile("cp.async.cg.shared.global [%0], [%1], 16, %2;"
                 :: "r"(dst), "l"(src), "r"(srcsize));
}
__device__ __forceinline__ void ldsm4(uint32_t* r, uint32_t addr) {
    asm volatile("ldmatrix.sync.aligned.m8n8.x4.shared.b16 {%0,%1,%2,%3}, [%4];"
                 : "=r"(r[0]), "=r"(r[1]), "=r"(r[2]), "=r"(r[3]) : "r"(addr));
}
__device__ __forceinline__ void mma16816(float* d, const uint32_t* a, uint32_t b0, uint32_t b1) {
    asm volatile("mma.sync.aligned.m16n8k16.row.col.f32.bf16.bf16.f32 "
                 "{%0,%1,%2,%3}, {%4,%5,%6,%7}, {%8,%9}, {%0,%1,%2,%3};"
                 : "+f"(d[0]), "+f"(d[1]), "+f"(d[2]), "+f"(d[3])
                 : "r"(a[0]), "r"(a[1]), "r"(a[2]), "r"(a[3]), "r"(b0), "r"(b1));
}
__device__ __forceinline__ void split_pair(float v, __nv_bfloat16& h, __nv_bfloat16& l) {
    h = __float2bfloat16_rn(v);
    l = __float2bfloat16_rn(v - __bfloat162float(h));
}
__device__ __forceinline__ float sigmoidf_(float x) { return 1.f / (1.f + expf(-x)); }

// ---------------------------------------------------------------------------
// Weight packing (interleaved output columns)
// ---------------------------------------------------------------------------
__global__ void pack_wzhT(const float* __restrict__ Wz, const float* __restrict__ Wh) {
    int idx = blockIdx.x * blockDim.x + threadIdx.x;
    if (idx >= H2 * Edim) return;
    int c = idx / Edim, k = idx - c * Edim;
    int j = c >> 1;
    float v = (c & 1) ? Wh[k * Hdim + j] : Wz[k * Hdim + j];
    split_pair(v, g_WzhT_h[idx], g_WzhT_l[idx]);
}

__global__ void pack_uzrT(const float* __restrict__ Uzl, const float* __restrict__ Uzr,
                          const float* __restrict__ Url, const float* __restrict__ Urr) {
    int idx = blockIdx.x * blockDim.x + threadIdx.x;
    if (idx >= H2 * H2) return;
    int c = idx >> 11, k = idx & (H2 - 1);
    int j = c >> 1, kk = k & (Hdim - 1);
    float v;
    if ((c & 1) == 0) v = (k < Hdim) ? Uzl[(size_t)k * Hdim + j] : Uzr[(size_t)kk * Hdim + j];
    else              v = (k < Hdim) ? Url[(size_t)k * Hdim + j] : Urr[(size_t)kk * Hdim + j];
    split_pair(v, g_UzrT_h[idx], g_UzrT_l[idx]);
}

__global__ void pack_uhT(const float* __restrict__ Uhl, const float* __restrict__ Uhr) {
    int idx = blockIdx.x * blockDim.x + threadIdx.x;
    if (idx >= Hdim * H2) return;
    int j = idx >> 11, k = idx & (H2 - 1);
    float v = (k < Hdim) ? Uhl[(size_t)k * Hdim + j] : Uhr[(size_t)(k - Hdim) * Hdim + j];
    split_pair(v, g_UhT_h[idx], g_UhT_l[idx]);
}

__global__ void pack_bias(const float* bz, const float* bzl, const float* bzr,
                          const float* br, const float* brl, const float* brr,
                          const float* bh, const float* bhl, const float* bhr) {
    int j = blockIdx.x * blockDim.x + threadIdx.x;
    if (j >= Hdim) return;
    g_bz[j] = bz[j] + bzl[j] + bzr[j];
    g_br[j] = br[j] + brl[j] + brr[j];
    g_bh[j] = bh[j] + bhl[j] + bhr[j];
}

__global__ void gather_split(const int* __restrict__ tokens, const float* __restrict__ emb) {
    int t = blockIdx.x * blockDim.x + threadIdx.x;
    if (t >= Bsz * Lseq * (Edim / 2)) return;
    int m = t / (Edim / 2), k2 = (t - m * (Edim / 2)) * 2;
    float2 v = *reinterpret_cast<const float2*>(emb + (size_t)tokens[m] * Edim + k2);
    __nv_bfloat16 h0, l0, h1, l1;
    split_pair(v.x, h0, l0);
    split_pair(v.y, h1, l1);
    size_t o = (size_t)m * Edim + k2;
    *reinterpret_cast<__nv_bfloat162*>(&g_Wh[o]) = __nv_bfloat162(h0, h1);
    *reinterpret_cast<__nv_bfloat162*>(&g_Wl[o]) = __nv_bfloat162(l0, l1);
}

// ---------------------------------------------------------------------------
// bf16-split GEMM (3 passes AhBh+AhBl+AlBh), CTA 128x256, 8 warps (64x64),
// BK=32, 3-stage single-sync cp.async pipeline, split-K via blockIdx.z.
// MODE 0: write C partial slab.  MODE 1: leaf fused.  MODE 2: merge1 fused.
// MODE 3: merge2 fused.
// ---------------------------------------------------------------------------
#define BKE 32
#define STAGE_BYTES 49152
#define OFF_AH 0
#define OFF_AL 8192
#define OFF_BH 16384
#define OFF_BL 32768
#define GEMM_SMEM (3 * STAGE_BYTES)

template <int MODE>
__global__ __launch_bounds__(256)
void mmagemm(const __nv_bfloat16* __restrict__ Ah, const __nv_bfloat16* __restrict__ Al,
             const __nv_bfloat16* __restrict__ Bh, const __nv_bfloat16* __restrict__ Bl,
             float* __restrict__ C, int M, int N, int Kfull, int Kp,
             const float* __restrict__ X,
             float* __restrict__ OUT,
             __nv_bfloat16* __restrict__ OUTh, __nv_bfloat16* __restrict__ OUTl) {
    extern __shared__ char smem[];
    const uint32_t sb = smem_u32(smem);
    const int tid = threadIdx.x, wid = tid >> 5, lane = tid & 31;
    const int bm = blockIdx.y * 128, bn = blockIdx.x * 256;
    const int ksl = blockIdx.z;
    const int kbase = ksl * Kp;

    // A cp.async mapping: row = tid>>1, k-half = (tid&1)*32B, two 16B chunks
    const int ld_row = tid >> 1;
    const uint32_t ld_kb = (uint32_t)(tid & 1) * 32u;
    const int a_gr = bm + ld_row;
    const uint32_t a_sz = (a_gr < M) ? 16u : 0u;
    const int a_cl = (a_gr < M) ? a_gr : 0;
    const __nv_bfloat16* ah_src = Ah + (size_t)a_cl * Kfull + kbase;
    const __nv_bfloat16* al_src = Al + (size_t)a_cl * Kfull + kbase;
    const uint32_t a_dst0 = swz64((uint32_t)ld_row, ld_kb);
    const uint32_t a_dst1 = swz64((uint32_t)ld_row, ld_kb + 16u);
    const int a_ke = (int)(ld_kb >> 1);
    // B cp.async mapping: row = tid (0..255), full 64B row (4 chunks)
    const __nv_bfloat16* bh_src = Bh + (size_t)(bn + tid) * Kfull + kbase;
    const __nv_bfloat16* bl_src = Bl + (size_t)(bn + tid) * Kfull + kbase;
    uint32_t b_dst[4];
    #pragma unroll
    for (int j = 0; j < 4; j++) b_dst[j] = swz64((uint32_t)tid, (uint32_t)j * 16u);

    // ldmatrix lane mappings
    const uint32_t a_lr = (uint32_t)(lane & 15);
    const uint32_t a_lb = (uint32_t)(lane >> 4) * 16u;
    const uint32_t b_lr = (uint32_t)((lane & 7) + ((lane >> 4) << 3));
    const uint32_t b_lb = (uint32_t)((lane >> 3) & 1) * 16u;
    const uint32_t wm = (uint32_t)(wid >> 2) * 64u;
    const uint32_t wn = (uint32_t)(wid & 3) * 64u;

    float acc[4][8][4];
    #pragma unroll
    for (int i = 0; i < 4; i++)
        #pragma unroll
        for (int j = 0; j < 8; j++)
            #pragma unroll
            for (int q = 0; q < 4; q++) acc[i][j][q] = 0.f;

    const int NC = Kp / BKE;

    auto load_stage = [&](int s, int c) {
        const uint32_t base = sb + (uint32_t)s * STAGE_BYTES;
        const int ka = c * BKE + a_ke;
        cp16(base + OFF_AH + a_dst0, ah_src + ka,     a_sz);
        cp16(base + OFF_AH + a_dst1, ah_src + ka + 8, a_sz);
        cp16(base + OFF_AL + a_dst0, al_src + ka,     a_sz);
        cp16(base + OFF_AL + a_dst1, al_src + ka + 8, a_sz);
        const int kb0 = c * BKE;
        #pragma unroll
        for (int j = 0; j < 4; j++) {
            cp16(base + OFF_BH + b_dst[j], bh_src + kb0 + j * 8, 16u);
            cp16(base + OFF_BL + b_dst[j], bl_src + kb0 + j * 8, 16u);
        }
        asm volatile("cp.async.commit_group;");
    };

    load_stage(0, 0);
    if (NC > 1) load_stage(1, 1);

    for (int c = 0; c < NC; c++) {
        if (c + 1 < NC) asm volatile("cp.async.wait_group 1;");
        else            asm volatile("cp.async.wait_group 0;");
        __syncthreads();
        // Single-sync multistage: the buffer (c+2)%3's readers finished at
        // this barrier (they consumed chunk c-1), so refill needs no 2nd sync.
        if (c + 2 < NC) load_stage((c + 2) % 3, c + 2);

        const uint32_t base = sb + (uint32_t)(c % 3) * STAGE_BYTES;
        #pragma unroll
        for (int ks = 0; ks < 2; ks++) {
            const uint32_t kb = (uint32_t)ks * 32u;
            uint32_t a[16], bh[16], bl[16];
            #pragma unroll
            for (int f = 0; f < 4; f++) {
                ldsm4(&bh[f * 4], base + OFF_BH + swz64(wn + f * 16u + b_lr, kb + b_lb));
                ldsm4(&bl[f * 4], base + OFF_BL + swz64(wn + f * 16u + b_lr, kb + b_lb));
            }
            #pragma unroll
            for (int mi = 0; mi < 4; mi++)
                ldsm4(&a[mi * 4], base + OFF_AH + swz64(wm + mi * 16u + a_lr, kb + a_lb));
            // pass 1: Ah * Bh
            #pragma unroll
            for (int mi = 0; mi < 4; mi++)
                #pragma unroll
                for (int ni = 0; ni < 8; ni++)
                    mma16816(acc[mi][ni], &a[mi * 4],
                             bh[(ni >> 1) * 4 + (ni & 1) * 2], bh[(ni >> 1) * 4 + (ni & 1) * 2 + 1]);
            // pass 2: Ah * Bl, with a_lo ldsm interleaved per-mi (early issue)
            #pragma unroll
            for (int mi = 0; mi < 4; mi++) {
                #pragma unroll
                for (int ni = 0; ni < 8; ni++)
                    mma16816(acc[mi][ni], &a[mi * 4],
                             bl[(ni >> 1) * 4 + (ni & 1) * 2], bl[(ni >> 1) * 4 + (ni & 1) * 2 + 1]);
                ldsm4(&a[mi * 4], base + OFF_AL + swz64(wm + mi * 16u + a_lr, kb + a_lb));
            }
            // pass 3: Al * Bh
            #pragma unroll
            for (int mi = 0; mi < 4; mi++)
                #pragma unroll
                for (int ni = 0; ni < 8; ni++)
                    mma16816(acc[mi][ni], &a[mi * 4],
                             bh[(ni >> 1) * 4 + (ni & 1) * 2], bh[(ni >> 1) * 4 + (ni & 1) * 2 + 1]);
        }
    }

    // ---------------- Epilogue ----------------
    const int er = lane >> 2, ec = (lane & 3) * 2;
    if (MODE == 0) {
        float* Cs = C + (size_t)ksl * (size_t)M * N;
        #pragma unroll
        for (int mi = 0; mi < 4; mi++) {
            #pragma unroll
            for (int ni = 0; ni < 8; ni++) {
                const int r0 = bm + (int)wm + mi * 16 + er;
                const int col = bn + (int)wn + ni * 8 + ec;
                if (r0 < M)
                    *reinterpret_cast<float2*>(Cs + (size_t)r0 * N + col)
                        = make_float2(acc[mi][ni][0], acc[mi][ni][1]);
                if (r0 + 8 < M)
                    *reinterpret_cast<float2*>(Cs + (size_t)(r0 + 8) * N + col)
                        = make_float2(acc[mi][ni][2], acc[mi][ni][3]);
            }
        }
    } else if (MODE == 1) {
        #pragma unroll
        for (int mi = 0; mi < 4; mi++) {
            #pragma unroll
            for (int ni = 0; ni < 8; ni++) {
                const int col = bn + (int)wn + ni * 8 + ec;
                const int j = col >> 1;
                const float bzj = g_bz[j], bhj = g_bh[j];
                #pragma unroll
                for (int rr = 0; rr < 2; rr++) {
                    const int row = bm + (int)wm + mi * 16 + er + rr * 8;
                    float z  = sigmoidf_(acc[mi][ni][rr * 2 + 0] + bzj);
                    float ht = tanhf(acc[mi][ni][rr * 2 + 1] + bhj);
                    float h  = (1.f - z) * ht;
                    size_t o = (size_t)row * Hdim + j;
                    OUT[o] = h;
                    __nv_bfloat16 hh, hl;
                    split_pair(h, hh, hl);
                    OUTh[o] = hh; OUTl[o] = hl;
                }
            }
        }
    } else if (MODE == 2) {
        #pragma unroll
        for (int mi = 0; mi < 4; mi++) {
            #pragma unroll
            for (int ni = 0; ni < 8; ni++) {
                const int col = bn + (int)wn + ni * 8 + ec;
                const int j = col >> 1;
                const float bzj = g_bz[j], brj = g_br[j];
                #pragma unroll
                for (int rr = 0; rr < 2; rr++) {
                    const int row = bm + (int)wm + mi * 16 + er + rr * 8;
                    if (row >= M) continue;
                    float z = sigmoidf_(acc[mi][ni][rr * 2 + 0] + bzj);
                    float r = sigmoidf_(acc[mi][ni][rr * 2 + 1] + brj);
                    g_Zb[(size_t)row * Hdim + j] = z;
                    size_t xb = (size_t)row * H2 + j;
                    float xl = X[xb], xr = X[xb + Hdim];
                    __nv_bfloat16 h, l;
                    split_pair(r * xl, h, l);
                    g_Qh[xb] = h; g_Ql[xb] = l;
                    split_pair(r * xr, h, l);
                    g_Qh[xb + Hdim] = h; g_Ql[xb + Hdim] = l;
                }
            }
        }
    } else {
        #pragma unroll
        for (int mi = 0; mi < 4; mi++) {
            #pragma unroll
            for (int ni = 0; ni < 8; ni++) {
                const int col = bn + (int)wn + ni * 8 + ec;
                const float bh0 = g_bh[col], bh1 = g_bh[col + 1];
                #pragma unroll
                for (int rr = 0; rr < 2; rr++) {
                    const int row = bm + (int)wm + mi * 16 + er + rr * 8;
                    if (row >= M) continue;
                    size_t o = (size_t)row * Hdim + col;
                    size_t xb = (size_t)row * H2 + col;
                    float2 z  = *reinterpret_cast<const float2*>(&g_Zb[o]);
                    float2 xl = *reinterpret_cast<const float2*>(&X[xb]);
                    float2 xr = *reinterpret_cast<const float2*>(&X[xb + Hdim]);
                    float h0 = z.x * (xl.x + xr.x) + (1.f - z.x) * tanhf(acc[mi][ni][rr * 2 + 0] + bh0);
                    float h1 = z.y * (xl.y + xr.y) + (1.f - z.y) * tanhf(acc[mi][ni][rr * 2 + 1] + bh1);
                    *reinterpret_cast<float2*>(&OUT[o]) = make_float2(h0, h1);
                    __nv_bfloat16 hh0, hl0, hh1, hl1;
                    split_pair(h0, hh0, hl0); split_pair(h1, hh1, hl1);
                    *reinterpret_cast<__nv_bfloat162*>(&OUTh[o]) = __nv_bfloat162(hh0, hh1);
                    *reinterpret_cast<__nv_bfloat162*>(&OUTl[o]) = __nv_bfloat162(hl0, hl1);
                }
            }
        }
    }
}

// ---------------------------------------------------------------------------
// Elementwise kernels for split-K (small) levels
// ---------------------------------------------------------------------------
__global__ void merge_ew1(const float* __restrict__ X, int M, int S, int total2) {
    int t = blockIdx.x * blockDim.x + threadIdx.x;
    if (t >= total2) return;
    int m = t >> 9, jj = (t & 511) * 2;
    const size_t slab = (size_t)M * H2;
    size_t pb = (size_t)m * H2 + 2 * jj;
    float4 p = *reinterpret_cast<const float4*>(&g_PRE[pb]);
    for (int s = 1; s < S; s++) {
        float4 q = *reinterpret_cast<const float4*>(&g_PRE[s * slab + pb]);
        p.x += q.x; p.y += q.y; p.z += q.z; p.w += q.w;
    }
    float z0 = sigmoidf_(p.x + g_bz[jj]), r0 = sigmoidf_(p.y + g_br[jj]);
    float z1 = sigmoidf_(p.z + g_bz[jj + 1]), r1 = sigmoidf_(p.w + g_br[jj + 1]);
    *reinterpret_cast<float2*>(&g_Zb[(size_t)m * Hdim + jj]) = make_float2(z0, z1);
    size_t xb = (size_t)m * H2 + jj;
    float2 xl = *reinterpret_cast<const float2*>(&X[xb]);
    float2 xr = *reinterpret_cast<const float2*>(&X[xb + Hdim]);
    __nv_bfloat16 h0, l0, h1, l1;
    split_pair(r0 * xl.x, h0, l0); split_pair(r1 * xl.y, h1, l1);
    *reinterpret_cast<__nv_bfloat162*>(&g_Qh[xb]) = __nv_bfloat162(h0, h1);
    *reinterpret_cast<__nv_bfloat162*>(&g_Ql[xb]) = __nv_bfloat162(l0, l1);
    split_pair(r0 * xr.x, h0, l0); split_pair(r1 * xr.y, h1, l1);
    *reinterpret_cast<__nv_bfloat162*>(&g_Qh[xb + Hdim]) = __nv_bfloat162(h0, h1);
    *reinterpret_cast<__nv_bfloat162*>(&g_Ql[xb + Hdim]) = __nv_bfloat162(l0, l1);
}

__global__ void merge_ew2(const float* __restrict__ X, float* __restrict__ OUT,
                          __nv_bfloat16* __restrict__ OUTh, __nv_bfloat16* __restrict__ OUTl,
                          int M, int S, int total2, int do_split) {
    int t = blockIdx.x * blockDim.x + threadIdx.x;
    if (t >= total2) return;
    int m = t >> 9, j = (t & 511) * 2;
    size_t o = (size_t)m * Hdim + j;
    const size_t slab = (size_t)M * Hdim;
    float2 ah = *reinterpret_cast<const float2*>(&g_PRE[o]);
    for (int s = 1; s < S; s++) {
        float2 a = *reinterpret_cast<const float2*>(&g_PRE[s * slab + o]);
        ah.x += a.x; ah.y += a.y;
    }
    size_t xb = (size_t)m * H2 + j;
    float2 z  = *reinterpret_cast<const float2*>(&g_Zb[o]);
    float2 xl = *reinterpret_cast<const float2*>(&X[xb]);
    float2 xr = *reinterpret_cast<const float2*>(&X[xb + Hdim]);
    float h0 = z.x * (xl.x + xr.x) + (1.f - z.x) * tanhf(ah.x + g_bh[j]);
    float h1 = z.y * (xl.y + xr.y) + (1.f - z.y) * tanhf(ah.y + g_bh[j + 1]);
    *reinterpret_cast<float2*>(&OUT[o]) = make_float2(h0, h1);
    if (do_split) {
        __nv_bfloat16 hh0, hl0, hh1, hl1;
        split_pair(h0, hh0, hl0); split_pair(h1, hh1, hl1);
        *reinterpret_cast<__nv_bfloat162*>(&OUTh[o]) = __nv_bfloat162(hh0, hh1);
        *reinterpret_cast<__nv_bfloat162*>(&OUTl[o]) = __nv_bfloat162(hl0, hl1);
    }
}

// ---------------------------------------------------------------------------
// Launch
// ---------------------------------------------------------------------------
extern "C" void kernel_launch(void* const* d_in, const int* in_sizes, int n_in,
                              void* d_out, int out_size) {
    const int*   tokens = (const int*)  d_in[0];
    const float* emb    = (const float*)d_in[1];
    const float* W_z  = (const float*)d_in[2];
    const float* b_z  = (const float*)d_in[3];
    const float* U_zl = (const float*)d_in[4];
    const float* b_zl = (const float*)d_in[5];
    const float* U_zr = (const float*)d_in[6];
    const float* b_zr = (const float*)d_in[7];
    const float* b_r  = (const float*)d_in[9];
    const float* U_rl = (const float*)d_in[10];
    const float* b_rl = (const float*)d_in[11];
    const float* U_rr = (const float*)d_in[12];
    const float* b_rr = (const float*)d_in[13];
    const float* W_h  = (const float*)d_in[14];
    const float* b_h  = (const float*)d_in[15];
    const float* U_hl = (const float*)d_in[16];
    const float* b_hl = (const float*)d_in[17];
    const float* U_hr = (const float*)d_in[18];
    const float* b_hr = (const float*)d_in[19];

    float *PRE, *H0, *H1;
    __nv_bfloat16 *Wh, *Wl, *H0h, *H0l, *H1h, *H1l, *Qh, *Ql;
    __nv_bfloat16 *WzhTh, *WzhTl, *UzrTh, *UzrTl, *UhTh, *UhTl;
    cudaGetSymbolAddress((void**)&PRE, g_PRE);
    cudaGetSymbolAddress((void**)&H0,  g_H0);
    cudaGetSymbolAddress((void**)&H1,  g_H1);
    cudaGetSymbolAddress((void**)&Wh,  g_Wh);
    cudaGetSymbolAddress((void**)&Wl,  g_Wl);
    cudaGetSymbolAddress((void**)&H0h, g_H0h);
    cudaGetSymbolAddress((void**)&H0l, g_H0l);
    cudaGetSymbolAddress((void**)&H1h, g_H1h);
    cudaGetSymbolAddress((void**)&H1l, g_H1l);
    cudaGetSymbolAddress((void**)&Qh,  g_Qh);
    cudaGetSymbolAddress((void**)&Ql,  g_Ql);
    cudaGetSymbolAddress((void**)&WzhTh, g_WzhT_h);
    cudaGetSymbolAddress((void**)&WzhTl, g_WzhT_l);
    cudaGetSymbolAddress((void**)&UzrTh, g_UzrT_h);
    cudaGetSymbolAddress((void**)&UzrTl, g_UzrT_l);
    cudaGetSymbolAddress((void**)&UhTh,  g_UhT_h);
    cudaGetSymbolAddress((void**)&UhTl,  g_UhT_l);

    cudaFuncSetAttribute(mmagemm<0>, cudaFuncAttributeMaxDynamicSharedMemorySize, GEMM_SMEM);
    cudaFuncSetAttribute(mmagemm<1>, cudaFuncAttributeMaxDynamicSharedMemorySize, GEMM_SMEM);
    cudaFuncSetAttribute(mmagemm<2>, cudaFuncAttributeMaxDynamicSharedMemorySize, GEMM_SMEM);
    cudaFuncSetAttribute(mmagemm<3>, cudaFuncAttributeMaxDynamicSharedMemorySize, GEMM_SMEM);

    const int Mleaf = Bsz * Lseq;  // 32768

    // Order chosen so the leaf GEMM is launch index 3 (the one ncu captures).
    pack_bias<<<(Hdim + 255) / 256, 256>>>(b_z, b_zl, b_zr, b_r, b_rl, b_rr, b_h, b_hl, b_hr);
    pack_wzhT<<<(H2 * Edim + 255) / 256, 256>>>(W_z, W_h);
    gather_split<<<(Mleaf * (Edim / 2) + 255) / 256, 256>>>(tokens, emb);

    {   // leaf fused: H0 = (1-z)*tanh(.), plus bf16 splits
        dim3 grid(H2 / 256, Mleaf / 128, 1);
        mmagemm<1><<<grid, 256, GEMM_SMEM>>>(Wh, Wl, WzhTh, WzhTl, nullptr,
                                             Mleaf, H2, Edim, Edim,
                                             nullptr, H0, H0h, H0l);
    }

    pack_uzrT<<<(H2 * H2 + 255) / 256, 256>>>(U_zl, U_zr, U_rl, U_rr);
    pack_uhT <<<(Hdim * H2 + 255) / 256, 256>>>(U_hl, U_hr);

    // --- merge levels ---
    float* cur = H0;
    __nv_bfloat16 *curh = H0h, *curl = H0l;
    for (int n = Lseq; n > 1; n >>= 1) {
        const int M = Bsz * (n / 2);
        const bool last = (n == 2);
        float* out = last ? (float*)d_out : ((cur == H0) ? H1 : H0);
        __nv_bfloat16* outh = (cur == H0) ? H1h : H0h;
        __nv_bfloat16* outl = (cur == H0) ? H1l : H0l;
        const int total2 = M * (Hdim / 2);
        const int gy = (M + 127) / 128;

        if (M >= 2048) {
            dim3 g1(H2 / 256, gy, 1);
            mmagemm<2><<<g1, 256, GEMM_SMEM>>>(curh, curl, UzrTh, UzrTl, nullptr,
                                               M, H2, H2, H2, cur, nullptr, nullptr, nullptr);
            dim3 g2(Hdim / 256, gy, 1);
            mmagemm<3><<<g2, 256, GEMM_SMEM>>>(Qh, Ql, UhTh, UhTl, nullptr,
                                               M, Hdim, H2, H2, cur, out, outh, outl);
        } else {
            int S = 2048 / M; if (S > 16) S = 16;
            const int Kp = H2 / S;
            dim3 g1(H2 / 256, gy, S);
            mmagemm<0><<<g1, 256, GEMM_SMEM>>>(curh, curl, UzrTh, UzrTl, PRE,
                                               M, H2, H2, Kp, nullptr, nullptr, nullptr, nullptr);
            merge_ew1<<<(total2 + 255) / 256, 256>>>(cur, M, S, total2);
            dim3 g2(Hdim / 256, gy, S);
            mmagemm<0><<<g2, 256, GEMM_SMEM>>>(Qh, Ql, UhTh, UhTl, PRE,
                                               M, Hdim, H2, Kp, nullptr, nullptr, nullptr, nullptr);
            merge_ew2<<<(total2 + 255) / 256, 256>>>(cur, out, outh, outl, M, S, total2, last ? 0 : 1);
        }
        cur = out; curh = outh; curl = outl;
    }
}

// round 10
// speedup vs baseline: 1.3466x; 1.3466x over previous
#include <cuda_runtime.h>
#include <cuda_bf16.h>
#include <math.h>
#include <cstdint>

#define Bsz   64
#define Lseq  512
#define Edim  512
#define Hdim  1024
#define H2    2048

// ---------------------------------------------------------------------------
// Scratch (device globals; no runtime allocation allowed)
// ---------------------------------------------------------------------------
__device__ float g_PRE[4u * 2048u * 2048u]; // split-K partial slabs (small levels only)
__device__ float g_Zb [16384u * 1024u];     // z gate per pair
__device__ float g_H0 [32768u * 1024u];     // state ping (fp32)
__device__ float g_H1 [16384u * 1024u];     // state pong (fp32)
// bf16 hi/lo split activations
__device__ __nv_bfloat16 g_Wh [32768u * 512u];
__device__ __nv_bfloat16 g_Wl [32768u * 512u];
__device__ __nv_bfloat16 g_H0h[32768u * 1024u];
__device__ __nv_bfloat16 g_H0l[32768u * 1024u];
__device__ __nv_bfloat16 g_H1h[16384u * 1024u];
__device__ __nv_bfloat16 g_H1l[16384u * 1024u];
__device__ __nv_bfloat16 g_Qh [16384u * 2048u];
__device__ __nv_bfloat16 g_Ql [16384u * 2048u];
// Transposed [N,K] weights split to bf16 hi/lo.
// WzhT: N interleaved as (z_j, h_j) pairs. UzrT: N interleaved as (z_j, r_j).
__device__ __nv_bfloat16 g_WzhT_h[(size_t)H2 * Edim];
__device__ __nv_bfloat16 g_WzhT_l[(size_t)H2 * Edim];
__device__ __nv_bfloat16 g_UzrT_h[(size_t)H2 * H2];
__device__ __nv_bfloat16 g_UzrT_l[(size_t)H2 * H2];
__device__ __nv_bfloat16 g_UhT_h [(size_t)Hdim * H2];
__device__ __nv_bfloat16 g_UhT_l [(size_t)Hdim * H2];
__device__ float g_bz[Hdim], g_br[Hdim], g_bh[Hdim];

// ---------------------------------------------------------------------------
// Helpers
// ---------------------------------------------------------------------------
__device__ __forceinline__ uint32_t smem_u32(const void* p) {
    uint32_t a;
    asm("{ .reg .u64 t; cvta.to.shared.u64 t, %1; cvt.u32.u64 %0, t; }" : "=r"(a) : "l"(p));
    return a;
}
__device__ __forceinline__ uint32_t swz64(uint32_t row, uint32_t byte) {
    return row * 64u + (byte ^ (((row >> 1) & 3u) << 4));
}
__device__ __forceinline__ void cp16(uint32_t dst, const void* src, uint32_t srcsize) {
    asm volatile("cp.async.cg.shared.global [%0], [%1], 16, %2;"
                 :: "r"(dst), "l"(src), "r"(srcsize));
}
__device__ __forceinline__ void ldsm4(uint32_t* r, uint32_t addr) {
    asm volatile("ldmatrix.sync.aligned.m8n8.x4.shared.b16 {%0,%1,%2,%3}, [%4];"
                 : "=r"(r[0]), "=r"(r[1]), "=r"(r[2]), "=r"(r[3]) : "r"(addr));
}
__device__ __forceinline__ void mma16816(float* d, const uint32_t* a, uint32_t b0, uint32_t b1) {
    asm volatile("mma.sync.aligned.m16n8k16.row.col.f32.bf16.bf16.f32 "
                 "{%0,%1,%2,%3}, {%4,%5,%6,%7}, {%8,%9}, {%0,%1,%2,%3};"
                 : "+f"(d[0]), "+f"(d[1]), "+f"(d[2]), "+f"(d[3])
                 : "r"(a[0]), "r"(a[1]), "r"(a[2]), "r"(a[3]), "r"(b0), "r"(b1));
}
__device__ __forceinline__ void split_pair(float v, __nv_bfloat16& h, __nv_bfloat16& l) {
    h = __float2bfloat16_rn(v);
    l = __float2bfloat16_rn(v - __bfloat162float(h));
}
__device__ __forceinline__ float sigmoidf_(float x) { return 1.f / (1.f + expf(-x)); }

// ---------------------------------------------------------------------------
// Weight packing (interleaved output columns)
// ---------------------------------------------------------------------------
__global__ void pack_wzhT(const float* __restrict__ Wz, const float* __restrict__ Wh) {
    int idx = blockIdx.x * blockDim.x + threadIdx.x;
    if (idx >= H2 * Edim) return;
    int c = idx / Edim, k = idx - c * Edim;
    int j = c >> 1;
    float v = (c & 1) ? Wh[k * Hdim + j] : Wz[k * Hdim + j];
    split_pair(v, g_WzhT_h[idx], g_WzhT_l[idx]);
}

__global__ void pack_uzrT(const float* __restrict__ Uzl, const float* __restrict__ Uzr,
                          const float* __restrict__ Url, const float* __restrict__ Urr) {
    int idx = blockIdx.x * blockDim.x + threadIdx.x;
    if (idx >= H2 * H2) return;
    int c = idx >> 11, k = idx & (H2 - 1);
    int j = c >> 1, kk = k & (Hdim - 1);
    float v;
    if ((c & 1) == 0) v = (k < Hdim) ? Uzl[(size_t)k * Hdim + j] : Uzr[(size_t)kk * Hdim + j];
    else              v = (k < Hdim) ? Url[(size_t)k * Hdim + j] : Urr[(size_t)kk * Hdim + j];
    split_pair(v, g_UzrT_h[idx], g_UzrT_l[idx]);
}

__global__ void pack_uhT(const float* __restrict__ Uhl, const float* __restrict__ Uhr) {
    int idx = blockIdx.x * blockDim.x + threadIdx.x;
    if (idx >= Hdim * H2) return;
    int j = idx >> 11, k = idx & (H2 - 1);
    float v = (k < Hdim) ? Uhl[(size_t)k * Hdim + j] : Uhr[(size_t)(k - Hdim) * Hdim + j];
    split_pair(v, g_UhT_h[idx], g_UhT_l[idx]);
}

__global__ void pack_bias(const float* bz, const float* bzl, const float* bzr,
                          const float* br, const float* brl, const float* brr,
                          const float* bh, const float* bhl, const float* bhr) {
    int j = blockIdx.x * blockDim.x + threadIdx.x;
    if (j >= Hdim) return;
    g_bz[j] = bz[j] + bzl[j] + bzr[j];
    g_br[j] = br[j] + brl[j] + brr[j];
    g_bh[j] = bh[j] + bhl[j] + bhr[j];
}

__global__ void gather_split(const int* __restrict__ tokens, const float* __restrict__ emb) {
    int t = blockIdx.x * blockDim.x + threadIdx.x;
    if (t >= Bsz * Lseq * (Edim / 2)) return;
    int m = t / (Edim / 2), k2 = (t - m * (Edim / 2)) * 2;
    float2 v = *reinterpret_cast<const float2*>(emb + (size_t)tokens[m] * Edim + k2);
    __nv_bfloat16 h0, l0, h1, l1;
    split_pair(v.x, h0, l0);
    split_pair(v.y, h1, l1);
    size_t o = (size_t)m * Edim + k2;
    *reinterpret_cast<__nv_bfloat162*>(&g_Wh[o]) = __nv_bfloat162(h0, h1);
    *reinterpret_cast<__nv_bfloat162*>(&g_Wl[o]) = __nv_bfloat162(l0, l1);
}

// ---------------------------------------------------------------------------
// bf16-split GEMM (3 passes AhBh+AhBl+AlBh), CTA 128x128, 8 warps (64x32),
// BK=32, 3-stage single-sync cp.async pipeline, split-K via blockIdx.z.
// LDSMs interleaved into MMA streams to hide smem latency.
// MODE 0: C partial slab. MODE 1: leaf fused. MODE 2: merge1. MODE 3: merge2.
// ---------------------------------------------------------------------------
#define BKE 32
#define STAGE_BYTES 32768
#define OFF_AH 0
#define OFF_AL 8192
#define OFF_BH 16384
#define OFF_BL 24576
#define GEMM_SMEM (3 * STAGE_BYTES)

template <int MODE>
__global__ __launch_bounds__(256, 2)
void mmagemm(const __nv_bfloat16* __restrict__ Ah, const __nv_bfloat16* __restrict__ Al,
             const __nv_bfloat16* __restrict__ Bh, const __nv_bfloat16* __restrict__ Bl,
             float* __restrict__ C, int M, int N, int Kfull, int Kp,
             const float* __restrict__ X,
             float* __restrict__ OUT,
             __nv_bfloat16* __restrict__ OUTh, __nv_bfloat16* __restrict__ OUTl) {
    extern __shared__ char smem[];
    const uint32_t sb = smem_u32(smem);
    const int tid = threadIdx.x, wid = tid >> 5, lane = tid & 31;
    const int bm = blockIdx.y * 128, bn = blockIdx.x * 128;
    const int ksl = blockIdx.z;
    const int kbase = ksl * Kp;

    const int ld_row = tid >> 1;
    const uint32_t ld_kb = (uint32_t)(tid & 1) * 32u;
    const int a_gr = bm + ld_row;
    const uint32_t a_sz = (a_gr < M) ? 16u : 0u;
    const int a_cl = (a_gr < M) ? a_gr : 0;
    const __nv_bfloat16* ah_src = Ah + (size_t)a_cl * Kfull + kbase;
    const __nv_bfloat16* al_src = Al + (size_t)a_cl * Kfull + kbase;
    const __nv_bfloat16* bh_src = Bh + (size_t)(bn + ld_row) * Kfull + kbase;
    const __nv_bfloat16* bl_src = Bl + (size_t)(bn + ld_row) * Kfull + kbase;
    const uint32_t dst0 = swz64((uint32_t)ld_row, ld_kb);
    const uint32_t dst1 = swz64((uint32_t)ld_row, ld_kb + 16u);
    const int ld_ke = (int)(ld_kb >> 1);

    const uint32_t a_lr = (uint32_t)(lane & 15);
    const uint32_t a_lb = (uint32_t)(lane >> 4) * 16u;
    const uint32_t b_lr = (uint32_t)((lane & 7) + ((lane >> 4) << 3));
    const uint32_t b_lb = (uint32_t)((lane >> 3) & 1) * 16u;
    const uint32_t wm = (uint32_t)(wid >> 2) * 64u;
    const uint32_t wn = (uint32_t)(wid & 3) * 32u;

    float acc[4][4][4];
    #pragma unroll
    for (int i = 0; i < 4; i++)
        #pragma unroll
        for (int j = 0; j < 4; j++)
            #pragma unroll
            for (int q = 0; q < 4; q++) acc[i][j][q] = 0.f;

    const int NC = Kp / BKE;

    auto load_stage = [&](int s, int c) {
        const uint32_t base = sb + (uint32_t)s * STAGE_BYTES;
        const int ke = c * BKE + ld_ke;
        cp16(base + OFF_AH + dst0, ah_src + ke,     a_sz);
        cp16(base + OFF_AH + dst1, ah_src + ke + 8, a_sz);
        cp16(base + OFF_AL + dst0, al_src + ke,     a_sz);
        cp16(base + OFF_AL + dst1, al_src + ke + 8, a_sz);
        cp16(base + OFF_BH + dst0, bh_src + ke,     16u);
        cp16(base + OFF_BH + dst1, bh_src + ke + 8, 16u);
        cp16(base + OFF_BL + dst0, bl_src + ke,     16u);
        cp16(base + OFF_BL + dst1, bl_src + ke + 8, 16u);
        asm volatile("cp.async.commit_group;");
    };

    load_stage(0, 0);
    if (NC > 1) load_stage(1, 1);

    for (int c = 0; c < NC; c++) {
        if (c + 1 < NC) asm volatile("cp.async.wait_group 1;");
        else            asm volatile("cp.async.wait_group 0;");
        __syncthreads();
        // Single-sync multistage: buffer (c+2)%3's readers finished at this
        // barrier (they consumed chunk c-1), so refill needs no second sync.
        if (c + 2 < NC) load_stage((c + 2) % 3, c + 2);

        const uint32_t base = sb + (uint32_t)(c % 3) * STAGE_BYTES;
        #pragma unroll
        for (int ks = 0; ks < 2; ks++) {
            const uint32_t kb = (uint32_t)ks * 32u;
            uint32_t a[16], bh[8], bl[8];
            // minimal prologue: bh (2 ldsm) + a-hi (4 ldsm), then start MMAs
            #pragma unroll
            for (int p = 0; p < 2; p++)
                ldsm4(&bh[p * 4], base + OFF_BH + swz64(wn + p * 16u + b_lr, kb + b_lb));
            #pragma unroll
            for (int mi = 0; mi < 4; mi++)
                ldsm4(&a[mi * 4], base + OFF_AH + swz64(wm + mi * 16u + a_lr, kb + a_lb));
            // pass 1: Ah*Bh, bl ldsm interleaved into first two mi-groups
            #pragma unroll
            for (int mi = 0; mi < 4; mi++) {
                #pragma unroll
                for (int ni = 0; ni < 4; ni++)
                    mma16816(acc[mi][ni], &a[mi * 4],
                             bh[(ni >> 1) * 4 + (ni & 1) * 2], bh[(ni >> 1) * 4 + (ni & 1) * 2 + 1]);
                if (mi < 2)
                    ldsm4(&bl[mi * 4], base + OFF_BL + swz64(wn + mi * 16u + b_lr, kb + b_lb));
            }
            // pass 2: Ah*Bl, a-lo ldsm interleaved per-mi right after last use
            #pragma unroll
            for (int mi = 0; mi < 4; mi++) {
                #pragma unroll
                for (int ni = 0; ni < 4; ni++)
                    mma16816(acc[mi][ni], &a[mi * 4],
                             bl[(ni >> 1) * 4 + (ni & 1) * 2], bl[(ni >> 1) * 4 + (ni & 1) * 2 + 1]);
                ldsm4(&a[mi * 4], base + OFF_AL + swz64(wm + mi * 16u + a_lr, kb + a_lb));
            }
            // pass 3: Al*Bh
            #pragma unroll
            for (int mi = 0; mi < 4; mi++)
                #pragma unroll
                for (int ni = 0; ni < 4; ni++)
                    mma16816(acc[mi][ni], &a[mi * 4],
                             bh[(ni >> 1) * 4 + (ni & 1) * 2], bh[(ni >> 1) * 4 + (ni & 1) * 2 + 1]);
        }
    }

    // ---------------- Epilogue ----------------
    const int er = lane >> 2, ec = (lane & 3) * 2;
    if (MODE == 0) {
        float* Cs = C + (size_t)ksl * (size_t)M * N;
        #pragma unroll
        for (int mi = 0; mi < 4; mi++) {
            #pragma unroll
            for (int ni = 0; ni < 4; ni++) {
                const int r0 = bm + (int)wm + mi * 16 + er;
                const int col = bn + (int)wn + ni * 8 + ec;
                if (r0 < M)
                    *reinterpret_cast<float2*>(Cs + (size_t)r0 * N + col)
                        = make_float2(acc[mi][ni][0], acc[mi][ni][1]);
                if (r0 + 8 < M)
                    *reinterpret_cast<float2*>(Cs + (size_t)(r0 + 8) * N + col)
                        = make_float2(acc[mi][ni][2], acc[mi][ni][3]);
            }
        }
    } else if (MODE == 1) {
        #pragma unroll
        for (int mi = 0; mi < 4; mi++) {
            #pragma unroll
            for (int ni = 0; ni < 4; ni++) {
                const int col = bn + (int)wn + ni * 8 + ec;
                const int j = col >> 1;
                const float bzj = g_bz[j], bhj = g_bh[j];
                #pragma unroll
                for (int rr = 0; rr < 2; rr++) {
                    const int row = bm + (int)wm + mi * 16 + er + rr * 8;
                    float z  = sigmoidf_(acc[mi][ni][rr * 2 + 0] + bzj);
                    float ht = tanhf(acc[mi][ni][rr * 2 + 1] + bhj);
                    float h  = (1.f - z) * ht;
                    size_t o = (size_t)row * Hdim + j;
                    OUT[o] = h;
                    __nv_bfloat16 hh, hl;
                    split_pair(h, hh, hl);
                    OUTh[o] = hh; OUTl[o] = hl;
                }
            }
        }
    } else if (MODE == 2) {
        #pragma unroll
        for (int mi = 0; mi < 4; mi++) {
            #pragma unroll
            for (int ni = 0; ni < 4; ni++) {
                const int col = bn + (int)wn + ni * 8 + ec;
                const int j = col >> 1;
                const float bzj = g_bz[j], brj = g_br[j];
                #pragma unroll
                for (int rr = 0; rr < 2; rr++) {
                    const int row = bm + (int)wm + mi * 16 + er + rr * 8;
                    if (row >= M) continue;
                    float z = sigmoidf_(acc[mi][ni][rr * 2 + 0] + bzj);
                    float r = sigmoidf_(acc[mi][ni][rr * 2 + 1] + brj);
                    g_Zb[(size_t)row * Hdim + j] = z;
                    size_t xb = (size_t)row * H2 + j;
                    float xl = X[xb], xr = X[xb + Hdim];
                    __nv_bfloat16 h, l;
                    split_pair(r * xl, h, l);
                    g_Qh[xb] = h; g_Ql[xb] = l;
                    split_pair(r * xr, h, l);
                    g_Qh[xb + Hdim] = h; g_Ql[xb + Hdim] = l;
                }
            }
        }
    } else {
        #pragma unroll
        for (int mi = 0; mi < 4; mi++) {
            #pragma unroll
            for (int ni = 0; ni < 4; ni++) {
                const int col = bn + (int)wn + ni * 8 + ec;
                const float bh0 = g_bh[col], bh1 = g_bh[col + 1];
                #pragma unroll
                for (int rr = 0; rr < 2; rr++) {
                    const int row = bm + (int)wm + mi * 16 + er + rr * 8;
                    if (row >= M) continue;
                    size_t o = (size_t)row * Hdim + col;
                    size_t xb = (size_t)row * H2 + col;
                    float2 z  = *reinterpret_cast<const float2*>(&g_Zb[o]);
                    float2 xl = *reinterpret_cast<const float2*>(&X[xb]);
                    float2 xr = *reinterpret_cast<const float2*>(&X[xb + Hdim]);
                    float h0 = z.x * (xl.x + xr.x) + (1.f - z.x) * tanhf(acc[mi][ni][rr * 2 + 0] + bh0);
                    float h1 = z.y * (xl.y + xr.y) + (1.f - z.y) * tanhf(acc[mi][ni][rr * 2 + 1] + bh1);
                    *reinterpret_cast<float2*>(&OUT[o]) = make_float2(h0, h1);
                    __nv_bfloat16 hh0, hl0, hh1, hl1;
                    split_pair(h0, hh0, hl0); split_pair(h1, hh1, hl1);
                    *reinterpret_cast<__nv_bfloat162*>(&OUTh[o]) = __nv_bfloat162(hh0, hh1);
                    *reinterpret_cast<__nv_bfloat162*>(&OUTl[o]) = __nv_bfloat162(hl0, hl1);
                }
            }
        }
    }
}

// ---------------------------------------------------------------------------
// Elementwise kernels for split-K (small) levels
// ---------------------------------------------------------------------------
__global__ void merge_ew1(const float* __restrict__ X, int M, int S, int total2) {
    int t = blockIdx.x * blockDim.x + threadIdx.x;
    if (t >= total2) return;
    int m = t >> 9, jj = (t & 511) * 2;
    const size_t slab = (size_t)M * H2;
    size_t pb = (size_t)m * H2 + 2 * jj;
    float4 p = *reinterpret_cast<const float4*>(&g_PRE[pb]);
    for (int s = 1; s < S; s++) {
        float4 q = *reinterpret_cast<const float4*>(&g_PRE[s * slab + pb]);
        p.x += q.x; p.y += q.y; p.z += q.z; p.w += q.w;
    }
    float z0 = sigmoidf_(p.x + g_bz[jj]), r0 = sigmoidf_(p.y + g_br[jj]);
    float z1 = sigmoidf_(p.z + g_bz[jj + 1]), r1 = sigmoidf_(p.w + g_br[jj + 1]);
    *reinterpret_cast<float2*>(&g_Zb[(size_t)m * Hdim + jj]) = make_float2(z0, z1);
    size_t xb = (size_t)m * H2 + jj;
    float2 xl = *reinterpret_cast<const float2*>(&X[xb]);
    float2 xr = *reinterpret_cast<const float2*>(&X[xb + Hdim]);
    __nv_bfloat16 h0, l0, h1, l1;
    split_pair(r0 * xl.x, h0, l0); split_pair(r1 * xl.y, h1, l1);
    *reinterpret_cast<__nv_bfloat162*>(&g_Qh[xb]) = __nv_bfloat162(h0, h1);
    *reinterpret_cast<__nv_bfloat162*>(&g_Ql[xb]) = __nv_bfloat162(l0, l1);
    split_pair(r0 * xr.x, h0, l0); split_pair(r1 * xr.y, h1, l1);
    *reinterpret_cast<__nv_bfloat162*>(&g_Qh[xb + Hdim]) = __nv_bfloat162(h0, h1);
    *reinterpret_cast<__nv_bfloat162*>(&g_Ql[xb + Hdim]) = __nv_bfloat162(l0, l1);
}

__global__ void merge_ew2(const float* __restrict__ X, float* __restrict__ OUT,
                          __nv_bfloat16* __restrict__ OUTh, __nv_bfloat16* __restrict__ OUTl,
                          int M, int S, int total2, int do_split) {
    int t = blockIdx.x * blockDim.x + threadIdx.x;
    if (t >= total2) return;
    int m = t >> 9, j = (t & 511) * 2;
    size_t o = (size_t)m * Hdim + j;
    const size_t slab = (size_t)M * Hdim;
    float2 ah = *reinterpret_cast<const float2*>(&g_PRE[o]);
    for (int s = 1; s < S; s++) {
        float2 a = *reinterpret_cast<const float2*>(&g_PRE[s * slab + o]);
        ah.x += a.x; ah.y += a.y;
    }
    size_t xb = (size_t)m * H2 + j;
    float2 z  = *reinterpret_cast<const float2*>(&g_Zb[o]);
    float2 xl = *reinterpret_cast<const float2*>(&X[xb]);
    float2 xr = *reinterpret_cast<const float2*>(&X[xb + Hdim]);
    float h0 = z.x * (xl.x + xr.x) + (1.f - z.x) * tanhf(ah.x + g_bh[j]);
    float h1 = z.y * (xl.y + xr.y) + (1.f - z.y) * tanhf(ah.y + g_bh[j + 1]);
    *reinterpret_cast<float2*>(&OUT[o]) = make_float2(h0, h1);
    if (do_split) {
        __nv_bfloat16 hh0, hl0, hh1, hl1;
        split_pair(h0, hh0, hl0); split_pair(h1, hh1, hl1);
        *reinterpret_cast<__nv_bfloat162*>(&OUTh[o]) = __nv_bfloat162(hh0, hh1);
        *reinterpret_cast<__nv_bfloat162*>(&OUTl[o]) = __nv_bfloat162(hl0, hl1);
    }
}

// ---------------------------------------------------------------------------
// Launch
// ---------------------------------------------------------------------------
extern "C" void kernel_launch(void* const* d_in, const int* in_sizes, int n_in,
                              void* d_out, int out_size) {
    const int*   tokens = (const int*)  d_in[0];
    const float* emb    = (const float*)d_in[1];
    const float* W_z  = (const float*)d_in[2];
    const float* b_z  = (const float*)d_in[3];
    const float* U_zl = (const float*)d_in[4];
    const float* b_zl = (const float*)d_in[5];
    const float* U_zr = (const float*)d_in[6];
    const float* b_zr = (const float*)d_in[7];
    const float* b_r  = (const float*)d_in[9];
    const float* U_rl = (const float*)d_in[10];
    const float* b_rl = (const float*)d_in[11];
    const float* U_rr = (const float*)d_in[12];
    const float* b_rr = (const float*)d_in[13];
    const float* W_h  = (const float*)d_in[14];
    const float* b_h  = (const float*)d_in[15];
    const float* U_hl = (const float*)d_in[16];
    const float* b_hl = (const float*)d_in[17];
    const float* U_hr = (const float*)d_in[18];
    const float* b_hr = (const float*)d_in[19];

    float *PRE, *H0, *H1;
    __nv_bfloat16 *Wh, *Wl, *H0h, *H0l, *H1h, *H1l, *Qh, *Ql;
    __nv_bfloat16 *WzhTh, *WzhTl, *UzrTh, *UzrTl, *UhTh, *UhTl;
    cudaGetSymbolAddress((void**)&PRE, g_PRE);
    cudaGetSymbolAddress((void**)&H0,  g_H0);
    cudaGetSymbolAddress((void**)&H1,  g_H1);
    cudaGetSymbolAddress((void**)&Wh,  g_Wh);
    cudaGetSymbolAddress((void**)&Wl,  g_Wl);
    cudaGetSymbolAddress((void**)&H0h, g_H0h);
    cudaGetSymbolAddress((void**)&H0l, g_H0l);
    cudaGetSymbolAddress((void**)&H1h, g_H1h);
    cudaGetSymbolAddress((void**)&H1l, g_H1l);
    cudaGetSymbolAddress((void**)&Qh,  g_Qh);
    cudaGetSymbolAddress((void**)&Ql,  g_Ql);
    cudaGetSymbolAddress((void**)&WzhTh, g_WzhT_h);
    cudaGetSymbolAddress((void**)&WzhTl, g_WzhT_l);
    cudaGetSymbolAddress((void**)&UzrTh, g_UzrT_h);
    cudaGetSymbolAddress((void**)&UzrTl, g_UzrT_l);
    cudaGetSymbolAddress((void**)&UhTh,  g_UhT_h);
    cudaGetSymbolAddress((void**)&UhTl,  g_UhT_l);

    cudaFuncSetAttribute(mmagemm<0>, cudaFuncAttributeMaxDynamicSharedMemorySize, GEMM_SMEM);
    cudaFuncSetAttribute(mmagemm<1>, cudaFuncAttributeMaxDynamicSharedMemorySize, GEMM_SMEM);
    cudaFuncSetAttribute(mmagemm<2>, cudaFuncAttributeMaxDynamicSharedMemorySize, GEMM_SMEM);
    cudaFuncSetAttribute(mmagemm<3>, cudaFuncAttributeMaxDynamicSharedMemorySize, GEMM_SMEM);

    const int Mleaf = Bsz * Lseq;  // 32768

    // Order chosen so the leaf GEMM is launch index 3 (the one ncu captures).
    pack_bias<<<(Hdim + 255) / 256, 256>>>(b_z, b_zl, b_zr, b_r, b_rl, b_rr, b_h, b_hl, b_hr);
    pack_wzhT<<<(H2 * Edim + 255) / 256, 256>>>(W_z, W_h);
    gather_split<<<(Mleaf * (Edim / 2) + 255) / 256, 256>>>(tokens, emb);

    {   // leaf fused: H0 = (1-z)*tanh(.), plus bf16 splits
        dim3 grid(H2 / 128, Mleaf / 128, 1);
        mmagemm<1><<<grid, 256, GEMM_SMEM>>>(Wh, Wl, WzhTh, WzhTl, nullptr,
                                             Mleaf, H2, Edim, Edim,
                                             nullptr, H0, H0h, H0l);
    }

    pack_uzrT<<<(H2 * H2 + 255) / 256, 256>>>(U_zl, U_zr, U_rl, U_rr);
    pack_uhT <<<(Hdim * H2 + 255) / 256, 256>>>(U_hl, U_hr);

    // --- merge levels ---
    float* cur = H0;
    __nv_bfloat16 *curh = H0h, *curl = H0l;
    for (int n = Lseq; n > 1; n >>= 1) {
        const int M = Bsz * (n / 2);
        const bool last = (n == 2);
        float* out = last ? (float*)d_out : ((cur == H0) ? H1 : H0);
        __nv_bfloat16* outh = (cur == H0) ? H1h : H0h;
        __nv_bfloat16* outl = (cur == H0) ? H1l : H0l;
        const int total2 = M * (Hdim / 2);
        const int gy = (M + 127) / 128;

        if (M >= 2048) {
            dim3 g1(H2 / 128, gy, 1);
            mmagemm<2><<<g1, 256, GEMM_SMEM>>>(curh, curl, UzrTh, UzrTl, nullptr,
                                               M, H2, H2, H2, cur, nullptr, nullptr, nullptr);
            dim3 g2(Hdim / 128, gy, 1);
            mmagemm<3><<<g2, 256, GEMM_SMEM>>>(Qh, Ql, UhTh, UhTl, nullptr,
                                               M, Hdim, H2, H2, cur, out, outh, outl);
        } else {
            int S = 2048 / M; if (S > 16) S = 16;
            const int Kp = H2 / S;
            dim3 g1(H2 / 128, gy, S);
            mmagemm<0><<<g1, 256, GEMM_SMEM>>>(curh, curl, UzrTh, UzrTl, PRE,
                                               M, H2, H2, Kp, nullptr, nullptr, nullptr, nullptr);
            merge_ew1<<<(total2 + 255) / 256, 256>>>(cur, M, S, total2);
            dim3 g2(Hdim / 128, gy, S);
            mmagemm<0><<<g2, 256, GEMM_SMEM>>>(Qh, Ql, UhTh, UhTl, PRE,
                                               M, Hdim, H2, Kp, nullptr, nullptr, nullptr, nullptr);
            merge_ew2<<<(total2 + 255) / 256, 256>>>(cur, out, outh, outl, M, S, total2, last ? 0 : 1);
        }
        cur = out; curh = outh; curl = outl;
    }
}

// round 11
// speedup vs baseline: 1.7835x; 1.3245x over previous
#include <cuda_runtime.h>
#include <cuda_fp16.h>
#include <math.h>
#include <cstdint>

#define Bsz   64
#define Lseq  512
#define Edim  512
#define Hdim  1024
#define H2    2048

// ---------------------------------------------------------------------------
// Scratch (device globals; no runtime allocation allowed)
// ---------------------------------------------------------------------------
__device__ float g_PRE[4u * 2048u * 2048u]; // split-K partial slabs (small levels only)
__device__ float g_Zb [16384u * 1024u];     // z gate per pair
__device__ float g_H0 [32768u * 1024u];     // state ping (fp32)
__device__ float g_H1 [16384u * 1024u];     // state pong (fp32)
// fp16 hi/lo split activations (A operands)
__device__ __half g_Wh [32768u * 512u];
__device__ __half g_Wl [32768u * 512u];
__device__ __half g_H0h[32768u * 1024u];
__device__ __half g_H0l[32768u * 1024u];
__device__ __half g_H1h[16384u * 1024u];
__device__ __half g_H1l[16384u * 1024u];
__device__ __half g_Qh [16384u * 2048u];
__device__ __half g_Ql [16384u * 2048u];
// Transposed [N,K] weights in single fp16 (B operands).
// WzhT: N interleaved as (z_j, h_j). UzrT: N interleaved as (z_j, r_j).
__device__ __half g_WzhT[(size_t)H2 * Edim];
__device__ __half g_UzrT[(size_t)H2 * H2];
__device__ __half g_UhT [(size_t)Hdim * H2];
__device__ float g_bz[Hdim], g_br[Hdim], g_bh[Hdim];

// ---------------------------------------------------------------------------
// Helpers
// ---------------------------------------------------------------------------
__device__ __forceinline__ uint32_t smem_u32(const void* p) {
    uint32_t a;
    asm("{ .reg .u64 t; cvta.to.shared.u64 t, %1; cvt.u32.u64 %0, t; }" : "=r"(a) : "l"(p));
    return a;
}
__device__ __forceinline__ uint32_t swz64(uint32_t row, uint32_t byte) {
    return row * 64u + (byte ^ (((row >> 1) & 3u) << 4));
}
__device__ __forceinline__ void cp16(uint32_t dst, const void* src, uint32_t srcsize) {
    asm volatile("cp.async.cg.shared.global [%0], [%1], 16, %2;"
                 :: "r"(dst), "l"(src), "r"(srcsize));
}
__device__ __forceinline__ void ldsm4(uint32_t* r, uint32_t addr) {
    asm volatile("ldmatrix.sync.aligned.m8n8.x4.shared.b16 {%0,%1,%2,%3}, [%4];"
                 : "=r"(r[0]), "=r"(r[1]), "=r"(r[2]), "=r"(r[3]) : "r"(addr));
}
__device__ __forceinline__ void mma16816(float* d, const uint32_t* a, uint32_t b0, uint32_t b1) {
    asm volatile("mma.sync.aligned.m16n8k16.row.col.f32.f16.f16.f32 "
                 "{%0,%1,%2,%3}, {%4,%5,%6,%7}, {%8,%9}, {%0,%1,%2,%3};"
                 : "+f"(d[0]), "+f"(d[1]), "+f"(d[2]), "+f"(d[3])
                 : "r"(a[0]), "r"(a[1]), "r"(a[2]), "r"(a[3]), "r"(b0), "r"(b1));
}
// fp16 hi/lo split of an fp32 value (hi+lo carries ~22 mantissa bits)
__device__ __forceinline__ void split_pair(float v, __half& h, __half& l) {
    h = __float2half_rn(v);
    l = __float2half_rn(v - __half2float(h));
}
__device__ __forceinline__ float sigmoidf_(float x) { return 1.f / (1.f + expf(-x)); }

// ---------------------------------------------------------------------------
// Weight packing (interleaved output columns; single fp16)
// ---------------------------------------------------------------------------
__global__ void pack_wzhT(const float* __restrict__ Wz, const float* __restrict__ Wh) {
    int idx = blockIdx.x * blockDim.x + threadIdx.x;
    if (idx >= H2 * Edim) return;
    int c = idx / Edim, k = idx - c * Edim;
    int j = c >> 1;
    float v = (c & 1) ? Wh[k * Hdim + j] : Wz[k * Hdim + j];
    g_WzhT[idx] = __float2half_rn(v);
}

__global__ void pack_uzrT(const float* __restrict__ Uzl, const float* __restrict__ Uzr,
                          const float* __restrict__ Url, const float* __restrict__ Urr) {
    int idx = blockIdx.x * blockDim.x + threadIdx.x;
    if (idx >= H2 * H2) return;
    int c = idx >> 11, k = idx & (H2 - 1);
    int j = c >> 1, kk = k & (Hdim - 1);
    float v;
    if ((c & 1) == 0) v = (k < Hdim) ? Uzl[(size_t)k * Hdim + j] : Uzr[(size_t)kk * Hdim + j];
    else              v = (k < Hdim) ? Url[(size_t)k * Hdim + j] : Urr[(size_t)kk * Hdim + j];
    g_UzrT[idx] = __float2half_rn(v);
}

__global__ void pack_uhT(const float* __restrict__ Uhl, const float* __restrict__ Uhr) {
    int idx = blockIdx.x * blockDim.x + threadIdx.x;
    if (idx >= Hdim * H2) return;
    int j = idx >> 11, k = idx & (H2 - 1);
    float v = (k < Hdim) ? Uhl[(size_t)k * Hdim + j] : Uhr[(size_t)(k - Hdim) * Hdim + j];
    g_UhT[idx] = __float2half_rn(v);
}

__global__ void pack_bias(const float* bz, const float* bzl, const float* bzr,
                          const float* br, const float* brl, const float* brr,
                          const float* bh, const float* bhl, const float* bhr) {
    int j = blockIdx.x * blockDim.x + threadIdx.x;
    if (j >= Hdim) return;
    g_bz[j] = bz[j] + bzl[j] + bzr[j];
    g_br[j] = br[j] + brl[j] + brr[j];
    g_bh[j] = bh[j] + bhl[j] + bhr[j];
}

__global__ void gather_split(const int* __restrict__ tokens, const float* __restrict__ emb) {
    int t = blockIdx.x * blockDim.x + threadIdx.x;
    if (t >= Bsz * Lseq * (Edim / 2)) return;
    int m = t / (Edim / 2), k2 = (t - m * (Edim / 2)) * 2;
    float2 v = *reinterpret_cast<const float2*>(emb + (size_t)tokens[m] * Edim + k2);
    __half h0, l0, h1, l1;
    split_pair(v.x, h0, l0);
    split_pair(v.y, h1, l1);
    size_t o = (size_t)m * Edim + k2;
    *reinterpret_cast<__half2*>(&g_Wh[o]) = __halves2half2(h0, h1);
    *reinterpret_cast<__half2*>(&g_Wl[o]) = __halves2half2(l0, l1);
}

// ---------------------------------------------------------------------------
// fp16-split GEMM (2 passes: Ah*B + Al*B), CTA 128x128, 8 warps (64x32),
// BK=32, 3-stage single-sync cp.async pipeline, split-K via blockIdx.z.
// A = fp16 hi/lo pair (error ~2^-24), B = single fp16 (error 2^-12).
// MODE 0: C partial slab. MODE 1: leaf fused. MODE 2: merge1. MODE 3: merge2.
// ---------------------------------------------------------------------------
#define BKE 32
#define STAGE_BYTES 24576
#define OFF_AH 0
#define OFF_AL 8192
#define OFF_B  16384
#define GEMM_SMEM (3 * STAGE_BYTES)

template <int MODE>
__global__ __launch_bounds__(256, 2)
void mmagemm(const __half* __restrict__ Ah, const __half* __restrict__ Al,
             const __half* __restrict__ B,
             float* __restrict__ C, int M, int N, int Kfull, int Kp,
             const float* __restrict__ X,
             float* __restrict__ OUT,
             __half* __restrict__ OUTh, __half* __restrict__ OUTl) {
    extern __shared__ char smem[];
    const uint32_t sb = smem_u32(smem);
    const int tid = threadIdx.x, wid = tid >> 5, lane = tid & 31;
    const int bm = blockIdx.y * 128, bn = blockIdx.x * 128;
    const int ksl = blockIdx.z;
    const int kbase = ksl * Kp;

    const int ld_row = tid >> 1;
    const uint32_t ld_kb = (uint32_t)(tid & 1) * 32u;
    const int a_gr = bm + ld_row;
    const uint32_t a_sz = (a_gr < M) ? 16u : 0u;
    const int a_cl = (a_gr < M) ? a_gr : 0;
    const __half* ah_src = Ah + (size_t)a_cl * Kfull + kbase;
    const __half* al_src = Al + (size_t)a_cl * Kfull + kbase;
    const __half* b_src  = B  + (size_t)(bn + ld_row) * Kfull + kbase;
    const uint32_t dst0 = swz64((uint32_t)ld_row, ld_kb);
    const uint32_t dst1 = swz64((uint32_t)ld_row, ld_kb + 16u);
    const int ld_ke = (int)(ld_kb >> 1);

    const uint32_t a_lr = (uint32_t)(lane & 15);
    const uint32_t a_lb = (uint32_t)(lane >> 4) * 16u;
    const uint32_t b_lr = (uint32_t)((lane & 7) + ((lane >> 4) << 3));
    const uint32_t b_lb = (uint32_t)((lane >> 3) & 1) * 16u;
    const uint32_t wm = (uint32_t)(wid >> 2) * 64u;
    const uint32_t wn = (uint32_t)(wid & 3) * 32u;

    float acc[4][4][4];
    #pragma unroll
    for (int i = 0; i < 4; i++)
        #pragma unroll
        for (int j = 0; j < 4; j++)
            #pragma unroll
            for (int q = 0; q < 4; q++) acc[i][j][q] = 0.f;

    const int NC = Kp / BKE;

    auto load_stage = [&](int s, int c) {
        const uint32_t base = sb + (uint32_t)s * STAGE_BYTES;
        const int ke = c * BKE + ld_ke;
        cp16(base + OFF_AH + dst0, ah_src + ke,     a_sz);
        cp16(base + OFF_AH + dst1, ah_src + ke + 8, a_sz);
        cp16(base + OFF_AL + dst0, al_src + ke,     a_sz);
        cp16(base + OFF_AL + dst1, al_src + ke + 8, a_sz);
        cp16(base + OFF_B  + dst0, b_src + ke,      16u);
        cp16(base + OFF_B  + dst1, b_src + ke + 8,  16u);
        asm volatile("cp.async.commit_group;");
    };

    load_stage(0, 0);
    if (NC > 1) load_stage(1, 1);

    for (int c = 0; c < NC; c++) {
        if (c + 1 < NC) asm volatile("cp.async.wait_group 1;");
        else            asm volatile("cp.async.wait_group 0;");
        __syncthreads();
        // Single-sync multistage: buffer (c+2)%3's readers finished at this
        // barrier (they consumed chunk c-1), so refill needs no second sync.
        if (c + 2 < NC) load_stage((c + 2) % 3, c + 2);

        const uint32_t base = sb + (uint32_t)(c % 3) * STAGE_BYTES;
        #pragma unroll
        for (int ks = 0; ks < 2; ks++) {
            const uint32_t kb = (uint32_t)ks * 32u;
            uint32_t a[16], bh[8];
            #pragma unroll
            for (int p = 0; p < 2; p++)
                ldsm4(&bh[p * 4], base + OFF_B + swz64(wn + p * 16u + b_lr, kb + b_lb));
            #pragma unroll
            for (int mi = 0; mi < 4; mi++)
                ldsm4(&a[mi * 4], base + OFF_AH + swz64(wm + mi * 16u + a_lr, kb + a_lb));
            // pass 1: Ah*B, a-lo ldsm interleaved per-mi right after last use
            #pragma unroll
            for (int mi = 0; mi < 4; mi++) {
                #pragma unroll
                for (int ni = 0; ni < 4; ni++)
                    mma16816(acc[mi][ni], &a[mi * 4],
                             bh[(ni >> 1) * 4 + (ni & 1) * 2], bh[(ni >> 1) * 4 + (ni & 1) * 2 + 1]);
                ldsm4(&a[mi * 4], base + OFF_AL + swz64(wm + mi * 16u + a_lr, kb + a_lb));
            }
            // pass 2: Al*B
            #pragma unroll
            for (int mi = 0; mi < 4; mi++)
                #pragma unroll
                for (int ni = 0; ni < 4; ni++)
                    mma16816(acc[mi][ni], &a[mi * 4],
                             bh[(ni >> 1) * 4 + (ni & 1) * 2], bh[(ni >> 1) * 4 + (ni & 1) * 2 + 1]);
        }
    }

    // ---------------- Epilogue ----------------
    const int er = lane >> 2, ec = (lane & 3) * 2;
    if (MODE == 0) {
        float* Cs = C + (size_t)ksl * (size_t)M * N;
        #pragma unroll
        for (int mi = 0; mi < 4; mi++) {
            #pragma unroll
            for (int ni = 0; ni < 4; ni++) {
                const int r0 = bm + (int)wm + mi * 16 + er;
                const int col = bn + (int)wn + ni * 8 + ec;
                if (r0 < M)
                    *reinterpret_cast<float2*>(Cs + (size_t)r0 * N + col)
                        = make_float2(acc[mi][ni][0], acc[mi][ni][1]);
                if (r0 + 8 < M)
                    *reinterpret_cast<float2*>(Cs + (size_t)(r0 + 8) * N + col)
                        = make_float2(acc[mi][ni][2], acc[mi][ni][3]);
            }
        }
    } else if (MODE == 1) {
        #pragma unroll
        for (int mi = 0; mi < 4; mi++) {
            #pragma unroll
            for (int ni = 0; ni < 4; ni++) {
                const int col = bn + (int)wn + ni * 8 + ec;
                const int j = col >> 1;
                const float bzj = g_bz[j], bhj = g_bh[j];
                #pragma unroll
                for (int rr = 0; rr < 2; rr++) {
                    const int row = bm + (int)wm + mi * 16 + er + rr * 8;
                    float z  = sigmoidf_(acc[mi][ni][rr * 2 + 0] + bzj);
                    float ht = tanhf(acc[mi][ni][rr * 2 + 1] + bhj);
                    float h  = (1.f - z) * ht;
                    size_t o = (size_t)row * Hdim + j;
                    OUT[o] = h;
                    __half hh, hl;
                    split_pair(h, hh, hl);
                    OUTh[o] = hh; OUTl[o] = hl;
                }
            }
        }
    } else if (MODE == 2) {
        #pragma unroll
        for (int mi = 0; mi < 4; mi++) {
            #pragma unroll
            for (int ni = 0; ni < 4; ni++) {
                const int col = bn + (int)wn + ni * 8 + ec;
                const int j = col >> 1;
                const float bzj = g_bz[j], brj = g_br[j];
                #pragma unroll
                for (int rr = 0; rr < 2; rr++) {
                    const int row = bm + (int)wm + mi * 16 + er + rr * 8;
                    if (row >= M) continue;
                    float z = sigmoidf_(acc[mi][ni][rr * 2 + 0] + bzj);
                    float r = sigmoidf_(acc[mi][ni][rr * 2 + 1] + brj);
                    g_Zb[(size_t)row * Hdim + j] = z;
                    size_t xb = (size_t)row * H2 + j;
                    float xl = X[xb], xr = X[xb + Hdim];
                    __half h, l;
                    split_pair(r * xl, h, l);
                    g_Qh[xb] = h; g_Ql[xb] = l;
                    split_pair(r * xr, h, l);
                    g_Qh[xb + Hdim] = h; g_Ql[xb + Hdim] = l;
                }
            }
        }
    } else {
        #pragma unroll
        for (int mi = 0; mi < 4; mi++) {
            #pragma unroll
            for (int ni = 0; ni < 4; ni++) {
                const int col = bn + (int)wn + ni * 8 + ec;
                const float bh0 = g_bh[col], bh1 = g_bh[col + 1];
                #pragma unroll
                for (int rr = 0; rr < 2; rr++) {
                    const int row = bm + (int)wm + mi * 16 + er + rr * 8;
                    if (row >= M) continue;
                    size_t o = (size_t)row * Hdim + col;
                    size_t xb = (size_t)row * H2 + col;
                    float2 z  = *reinterpret_cast<const float2*>(&g_Zb[o]);
                    float2 xl = *reinterpret_cast<const float2*>(&X[xb]);
                    float2 xr = *reinterpret_cast<const float2*>(&X[xb + Hdim]);
                    float h0 = z.x * (xl.x + xr.x) + (1.f - z.x) * tanhf(acc[mi][ni][rr * 2 + 0] + bh0);
                    float h1 = z.y * (xl.y + xr.y) + (1.f - z.y) * tanhf(acc[mi][ni][rr * 2 + 1] + bh1);
                    *reinterpret_cast<float2*>(&OUT[o]) = make_float2(h0, h1);
                    __half hh0, hl0, hh1, hl1;
                    split_pair(h0, hh0, hl0); split_pair(h1, hh1, hl1);
                    *reinterpret_cast<__half2*>(&OUTh[o]) = __halves2half2(hh0, hh1);
                    *reinterpret_cast<__half2*>(&OUTl[o]) = __halves2half2(hl0, hl1);
                }
            }
        }
    }
}

// ---------------------------------------------------------------------------
// Elementwise kernels for split-K (small) levels
// ---------------------------------------------------------------------------
__global__ void merge_ew1(const float* __restrict__ X, int M, int S, int total2) {
    int t = blockIdx.x * blockDim.x + threadIdx.x;
    if (t >= total2) return;
    int m = t >> 9, jj = (t & 511) * 2;
    const size_t slab = (size_t)M * H2;
    size_t pb = (size_t)m * H2 + 2 * jj;
    float4 p = *reinterpret_cast<const float4*>(&g_PRE[pb]);
    for (int s = 1; s < S; s++) {
        float4 q = *reinterpret_cast<const float4*>(&g_PRE[s * slab + pb]);
        p.x += q.x; p.y += q.y; p.z += q.z; p.w += q.w;
    }
    float z0 = sigmoidf_(p.x + g_bz[jj]), r0 = sigmoidf_(p.y + g_br[jj]);
    float z1 = sigmoidf_(p.z + g_bz[jj + 1]), r1 = sigmoidf_(p.w + g_br[jj + 1]);
    *reinterpret_cast<float2*>(&g_Zb[(size_t)m * Hdim + jj]) = make_float2(z0, z1);
    size_t xb = (size_t)m * H2 + jj;
    float2 xl = *reinterpret_cast<const float2*>(&X[xb]);
    float2 xr = *reinterpret_cast<const float2*>(&X[xb + Hdim]);
    __half h0, l0, h1, l1;
    split_pair(r0 * xl.x, h0, l0); split_pair(r1 * xl.y, h1, l1);
    *reinterpret_cast<__half2*>(&g_Qh[xb]) = __halves2half2(h0, h1);
    *reinterpret_cast<__half2*>(&g_Ql[xb]) = __halves2half2(l0, l1);
    split_pair(r0 * xr.x, h0, l0); split_pair(r1 * xr.y, h1, l1);
    *reinterpret_cast<__half2*>(&g_Qh[xb + Hdim]) = __halves2half2(h0, h1);
    *reinterpret_cast<__half2*>(&g_Ql[xb + Hdim]) = __halves2half2(l0, l1);
}

__global__ void merge_ew2(const float* __restrict__ X, float* __restrict__ OUT,
                          __half* __restrict__ OUTh, __half* __restrict__ OUTl,
                          int M, int S, int total2, int do_split) {
    int t = blockIdx.x * blockDim.x + threadIdx.x;
    if (t >= total2) return;
    int m = t >> 9, j = (t & 511) * 2;
    size_t o = (size_t)m * Hdim + j;
    const size_t slab = (size_t)M * Hdim;
    float2 ah = *reinterpret_cast<const float2*>(&g_PRE[o]);
    for (int s = 1; s < S; s++) {
        float2 a = *reinterpret_cast<const float2*>(&g_PRE[s * slab + o]);
        ah.x += a.x; ah.y += a.y;
    }
    size_t xb = (size_t)m * H2 + j;
    float2 z  = *reinterpret_cast<const float2*>(&g_Zb[o]);
    float2 xl = *reinterpret_cast<const float2*>(&X[xb]);
    float2 xr = *reinterpret_cast<const float2*>(&X[xb + Hdim]);
    float h0 = z.x * (xl.x + xr.x) + (1.f - z.x) * tanhf(ah.x + g_bh[j]);
    float h1 = z.y * (xl.y + xr.y) + (1.f - z.y) * tanhf(ah.y + g_bh[j + 1]);
    *reinterpret_cast<float2*>(&OUT[o]) = make_float2(h0, h1);
    if (do_split) {
        __half hh0, hl0, hh1, hl1;
        split_pair(h0, hh0, hl0); split_pair(h1, hh1, hl1);
        *reinterpret_cast<__half2*>(&OUTh[o]) = __halves2half2(hh0, hh1);
        *reinterpret_cast<__half2*>(&OUTl[o]) = __halves2half2(hl0, hl1);
    }
}

// ---------------------------------------------------------------------------
// Launch
// ---------------------------------------------------------------------------
extern "C" void kernel_launch(void* const* d_in, const int* in_sizes, int n_in,
                              void* d_out, int out_size) {
    const int*   tokens = (const int*)  d_in[0];
    const float* emb    = (const float*)d_in[1];
    const float* W_z  = (const float*)d_in[2];
    const float* b_z  = (const float*)d_in[3];
    const float* U_zl = (const float*)d_in[4];
    const float* b_zl = (const float*)d_in[5];
    const float* U_zr = (const float*)d_in[6];
    const float* b_zr = (const float*)d_in[7];
    const float* b_r  = (const float*)d_in[9];
    const float* U_rl = (const float*)d_in[10];
    const float* b_rl = (const float*)d_in[11];
    const float* U_rr = (const float*)d_in[12];
    const float* b_rr = (const float*)d_in[13];
    const float* W_h  = (const float*)d_in[14];
    const float* b_h  = (const float*)d_in[15];
    const float* U_hl = (const float*)d_in[16];
    const float* b_hl = (const float*)d_in[17];
    const float* U_hr = (const float*)d_in[18];
    const float* b_hr = (const float*)d_in[19];

    float *PRE, *H0, *H1;
    __half *Wh, *Wl, *H0h, *H0l, *H1h, *H1l, *Qh, *Ql;
    __half *WzhT, *UzrT, *UhT;
    cudaGetSymbolAddress((void**)&PRE, g_PRE);
    cudaGetSymbolAddress((void**)&H0,  g_H0);
    cudaGetSymbolAddress((void**)&H1,  g_H1);
    cudaGetSymbolAddress((void**)&Wh,  g_Wh);
    cudaGetSymbolAddress((void**)&Wl,  g_Wl);
    cudaGetSymbolAddress((void**)&H0h, g_H0h);
    cudaGetSymbolAddress((void**)&H0l, g_H0l);
    cudaGetSymbolAddress((void**)&H1h, g_H1h);
    cudaGetSymbolAddress((void**)&H1l, g_H1l);
    cudaGetSymbolAddress((void**)&Qh,  g_Qh);
    cudaGetSymbolAddress((void**)&Ql,  g_Ql);
    cudaGetSymbolAddress((void**)&WzhT, g_WzhT);
    cudaGetSymbolAddress((void**)&UzrT, g_UzrT);
    cudaGetSymbolAddress((void**)&UhT,  g_UhT);

    cudaFuncSetAttribute(mmagemm<0>, cudaFuncAttributeMaxDynamicSharedMemorySize, GEMM_SMEM);
    cudaFuncSetAttribute(mmagemm<1>, cudaFuncAttributeMaxDynamicSharedMemorySize, GEMM_SMEM);
    cudaFuncSetAttribute(mmagemm<2>, cudaFuncAttributeMaxDynamicSharedMemorySize, GEMM_SMEM);
    cudaFuncSetAttribute(mmagemm<3>, cudaFuncAttributeMaxDynamicSharedMemorySize, GEMM_SMEM);

    const int Mleaf = Bsz * Lseq;  // 32768

    // Order chosen so the leaf GEMM is launch index 3 (the one ncu captures).
    pack_bias<<<(Hdim + 255) / 256, 256>>>(b_z, b_zl, b_zr, b_r, b_rl, b_rr, b_h, b_hl, b_hr);
    pack_wzhT<<<(H2 * Edim + 255) / 256, 256>>>(W_z, W_h);
    gather_split<<<(Mleaf * (Edim / 2) + 255) / 256, 256>>>(tokens, emb);

    {   // leaf fused: H0 = (1-z)*tanh(.), plus fp16 splits
        dim3 grid(H2 / 128, Mleaf / 128, 1);
        mmagemm<1><<<grid, 256, GEMM_SMEM>>>(Wh, Wl, WzhT, nullptr,
                                             Mleaf, H2, Edim, Edim,
                                             nullptr, H0, H0h, H0l);
    }

    pack_uzrT<<<(H2 * H2 + 255) / 256, 256>>>(U_zl, U_zr, U_rl, U_rr);
    pack_uhT <<<(Hdim * H2 + 255) / 256, 256>>>(U_hl, U_hr);

    // --- merge levels ---
    float* cur = H0;
    __half *curh = H0h, *curl = H0l;
    for (int n = Lseq; n > 1; n >>= 1) {
        const int M = Bsz * (n / 2);
        const bool last = (n == 2);
        float* out = last ? (float*)d_out : ((cur == H0) ? H1 : H0);
        __half* outh = (cur == H0) ? H1h : H0h;
        __half* outl = (cur == H0) ? H1l : H0l;
        const int total2 = M * (Hdim / 2);
        const int gy = (M + 127) / 128;

        if (M >= 2048) {
            dim3 g1(H2 / 128, gy, 1);
            mmagemm<2><<<g1, 256, GEMM_SMEM>>>(curh, curl, UzrT, nullptr,
                                               M, H2, H2, H2, cur, nullptr, nullptr, nullptr);
            dim3 g2(Hdim / 128, gy, 1);
            mmagemm<3><<<g2, 256, GEMM_SMEM>>>(Qh, Ql, UhT, nullptr,
                                               M, Hdim, H2, H2, cur, out, outh, outl);
        } else {
            int S = 2048 / M; if (S > 16) S = 16;
            const int Kp = H2 / S;
            dim3 g1(H2 / 128, gy, S);
            mmagemm<0><<<g1, 256, GEMM_SMEM>>>(curh, curl, UzrT, PRE,
                                               M, H2, H2, Kp, nullptr, nullptr, nullptr, nullptr);
            merge_ew1<<<(total2 + 255) / 256, 256>>>(cur, M, S, total2);
            dim3 g2(Hdim / 128, gy, S);
            mmagemm<0><<<g2, 256, GEMM_SMEM>>>(Qh, Ql, UhT, PRE,
                                               M, Hdim, H2, Kp, nullptr, nullptr, nullptr, nullptr);
            merge_ew2<<<(total2 + 255) / 256, 256>>>(cur, out, outh, outl, M, S, total2, last ? 0 : 1);
        }
        cur = out; curh = outh; curl = outl;
    }
}